// round 1
// baseline (speedup 1.0000x reference)
#include <cuda_runtime.h>
#include <math.h>

#define NN 4096
#define DIN 256
#define DOUT 256
#define KH 3
#define RH 3
#define CAP 1024

// scratch (device globals: no allocation allowed)
__device__ float g_wx[KH * NN * DOUT];   // 12 MB
__device__ float g_al[KH * NN * 4];
__device__ float g_ar[KH * NN * 4];

// ---------------------------------------------------------------------------
// Kernel 1: wx[k] = x @ W_t[k]   (4096x256 @ 256x256, fp32, 64x64 tiles)
// ---------------------------------------------------------------------------
__global__ void gemm_wx_kernel(const float* __restrict__ x,
                               const float* __restrict__ Wt) {
    int k = blockIdx.z;
    const float* B = Wt + (size_t)k * DIN * DOUT;
    float* C = g_wx + (size_t)k * NN * DOUT;

    __shared__ float As[16][64];
    __shared__ float Bs[16][64];

    int tx = threadIdx.x;            // 0..255
    int row0 = blockIdx.y * 64;
    int col0 = blockIdx.x * 64;
    int tr = tx >> 4;                // 0..15
    int tc = tx & 15;                // 0..15

    float acc[4][4];
#pragma unroll
    for (int i = 0; i < 4; i++)
#pragma unroll
        for (int j = 0; j < 4; j++) acc[i][j] = 0.f;

    for (int kk = 0; kk < DIN; kk += 16) {
        // load A tile (64 rows x 16 k), transposed into As[k][row]
        {
            int r = tx >> 2;
            int c4 = (tx & 3) * 4;
            float4 v = *(const float4*)(x + (size_t)(row0 + r) * DIN + kk + c4);
            As[c4 + 0][r] = v.x;
            As[c4 + 1][r] = v.y;
            As[c4 + 2][r] = v.z;
            As[c4 + 3][r] = v.w;
        }
        // load B tile (16 k x 64 cols)
        {
            int rr = tx >> 4;
            int cc = tx & 15;
            float4 w = *(const float4*)(B + (size_t)(kk + rr) * DOUT + col0 + cc * 4);
            *(float4*)&Bs[rr][cc * 4] = w;
        }
        __syncthreads();
#pragma unroll
        for (int p = 0; p < 16; p++) {
            float4 a = *(float4*)&As[p][tr * 4];
            float4 b = *(float4*)&Bs[p][tc * 4];
            float av[4] = {a.x, a.y, a.z, a.w};
            float bv[4] = {b.x, b.y, b.z, b.w};
#pragma unroll
            for (int i = 0; i < 4; i++)
#pragma unroll
                for (int j = 0; j < 4; j++) acc[i][j] += av[i] * bv[j];
        }
        __syncthreads();
    }
#pragma unroll
    for (int i = 0; i < 4; i++) {
        float4 v = make_float4(acc[i][0], acc[i][1], acc[i][2], acc[i][3]);
        *(float4*)(C + (size_t)(row0 + tr * 4 + i) * DOUT + col0 + tc * 4) = v;
    }
}

// ---------------------------------------------------------------------------
// Kernel 2: al[k][n][j] = wx[k][n] . W_l[k][j],  ar same with W_r
// one block = 32 rows of one k; 256 threads = 32 rows x 8 outputs
// ---------------------------------------------------------------------------
__global__ void alar_kernel(const float* __restrict__ Wl,
                            const float* __restrict__ Wr) {
    int k = blockIdx.y;
    int n0 = blockIdx.x * 32;
    __shared__ float sx[32][DOUT + 1];

    const float* wx = g_wx + (size_t)k * NN * DOUT;
    for (int i = threadIdx.x; i < 32 * (DOUT / 4); i += blockDim.x) {
        int r = i / (DOUT / 4);
        int c = i % (DOUT / 4);
        float4 v = *(const float4*)(wx + (size_t)(n0 + r) * DOUT + c * 4);
        sx[r][c * 4 + 0] = v.x;
        sx[r][c * 4 + 1] = v.y;
        sx[r][c * 4 + 2] = v.z;
        sx[r][c * 4 + 3] = v.w;
    }
    __syncthreads();

    int n = threadIdx.x >> 3;
    int j = threadIdx.x & 7;
    const float* w = (j < 4) ? (Wl + (size_t)(k * 4 + j) * DOUT)
                             : (Wr + (size_t)(k * 4 + (j - 4)) * DOUT);
    float s = 0.f;
#pragma unroll 8
    for (int d = 0; d < DOUT; d++) s += sx[n][d] * w[d];

    if (j < 4)
        g_al[((size_t)k * NN + n0 + n) * 4 + j] = s;
    else
        g_ar[((size_t)k * NN + n0 + n) * 4 + (j - 4)] = s;
}

// ---------------------------------------------------------------------------
// Kernel 3: per-row fused attention (all 3 k in a single pass over masks)
// ---------------------------------------------------------------------------
__global__ void __launch_bounds__(256)
attn_kernel(const int* __restrict__ supports,
            const int* __restrict__ atten,
            float* __restrict__ out) {
    int n = blockIdx.x;
    int tid = threadIdx.x;
    int lane = tid & 31;
    int wid = tid >> 5;

    __shared__ unsigned s_list[CAP];
    __shared__ float s_p[3][CAP];
    __shared__ int s_warp[8];
    __shared__ int s_cnt;
    __shared__ float s_al[3][4];
    __shared__ float s_red[3][8];
    __shared__ float s_mx[3];
    __shared__ float s_inv[3];

    if (tid < 12) {
        int k = tid >> 2, j = tid & 3;
        s_al[k][j] = g_al[((size_t)k * NN + n) * 4 + j];
    }

    // ---- compaction pass: scan 6 mask rows, build edge list (deterministic)
    const int4* pa0 = (const int4*)(atten + ((size_t)0 * NN + n) * NN);
    const int4* pa1 = (const int4*)(atten + ((size_t)1 * NN + n) * NN);
    const int4* pa2 = (const int4*)(atten + ((size_t)2 * NN + n) * NN);
    const int4* ps0 = (const int4*)(supports + ((size_t)0 * NN + n) * NN);
    const int4* ps1 = (const int4*)(supports + ((size_t)1 * NN + n) * NN);
    const int4* ps2 = (const int4*)(supports + ((size_t)2 * NN + n) * NN);

    unsigned char codes[16];
    int cnt_local = 0;
#pragma unroll
    for (int it = 0; it < 4; it++) {
        int i = tid + it * 256;     // int4 index, m base = 4*i
        int4 a0 = pa0[i], a1 = pa1[i], a2 = pa2[i];
        int4 q0 = ps0[i], q1 = ps1[i], q2 = ps2[i];
        int aa0[4] = {a0.x, a0.y, a0.z, a0.w};
        int aa1[4] = {a1.x, a1.y, a1.z, a1.w};
        int aa2[4] = {a2.x, a2.y, a2.z, a2.w};
        int qq0[4] = {q0.x, q0.y, q0.z, q0.w};
        int qq1[4] = {q1.x, q1.y, q1.z, q1.w};
        int qq2[4] = {q2.x, q2.y, q2.z, q2.w};
#pragma unroll
        for (int j = 0; j < 4; j++) {
            int code = (aa0[j] ? 1 : 0) | (aa1[j] ? 2 : 0) | (aa2[j] ? 4 : 0) |
                       (qq0[j] ? 8 : 0) | (qq1[j] ? 16 : 0) | (qq2[j] ? 32 : 0);
            codes[it * 4 + j] = (unsigned char)code;
            cnt_local += (code != 0);
        }
    }

    // exclusive prefix sum of per-thread counts (256 threads)
    int incl = cnt_local;
#pragma unroll
    for (int o = 1; o < 32; o <<= 1) {
        int t = __shfl_up_sync(0xffffffffu, incl, o);
        if (lane >= o) incl += t;
    }
    if (lane == 31) s_warp[wid] = incl;
    __syncthreads();
    if (tid < 8) {
        int t = s_warp[tid];
        int p = t;
#pragma unroll
        for (int o = 1; o < 8; o <<= 1) {
            int u = __shfl_up_sync(0xffu, p, o);
            if (tid >= o) p += u;
        }
        s_warp[tid] = p - t;   // exclusive warp offset
    }
    __syncthreads();
    int off = s_warp[wid] + incl - cnt_local;
    if (tid == 255) s_cnt = off + cnt_local;
    __syncthreads();
    int cnt = s_cnt;
    if (cnt > CAP) cnt = CAP;

    // fill edge list
#pragma unroll
    for (int it = 0; it < 4; it++) {
#pragma unroll
        for (int j = 0; j < 4; j++) {
            int c = codes[it * 4 + j];
            if (c) {
                int m = (tid + it * 256) * 4 + j;
                if (off < CAP) s_list[off] = ((unsigned)m << 6) | (unsigned)c;
                off++;
            }
        }
    }
    __syncthreads();

    // ---- scores for all 3 k
    for (int e = tid; e < cnt; e += 256) {
        unsigned v = s_list[e];
        int m = (int)(v >> 6);
        int code = (int)(v & 63u);
#pragma unroll
        for (int k = 0; k < 3; k++) {
            float4 arv = *(const float4*)(g_ar + ((size_t)k * NN + m) * 4);
            float s = 0.f;
            if (code & 1) s += s_al[k][0] + arv.x;
            if (code & 2) s += s_al[k][1] + arv.y;
            if (code & 4) s += s_al[k][2] + arv.z;
            if (code & (8 << k)) s += s_al[k][3] + arv.w;
            s_p[k][e] = s;
        }
    }
    __syncthreads();

    // ---- max over valid (score != 0) per k
    float mx[3] = {-INFINITY, -INFINITY, -INFINITY};
    for (int e = tid; e < cnt; e += 256) {
#pragma unroll
        for (int k = 0; k < 3; k++) {
            float s = s_p[k][e];
            if (s != 0.f) mx[k] = fmaxf(mx[k], s);
        }
    }
#pragma unroll
    for (int k = 0; k < 3; k++)
#pragma unroll
        for (int o = 16; o; o >>= 1)
            mx[k] = fmaxf(mx[k], __shfl_xor_sync(0xffffffffu, mx[k], o));
    if (lane == 0) {
#pragma unroll
        for (int k = 0; k < 3; k++) s_red[k][wid] = mx[k];
    }
    __syncthreads();
    if (tid == 0) {
#pragma unroll
        for (int k = 0; k < 3; k++) {
            float m = s_red[k][0];
#pragma unroll
            for (int w = 1; w < 8; w++) m = fmaxf(m, s_red[k][w]);
            s_mx[k] = m;
        }
    }
    __syncthreads();

    // ---- exp + sum
    float mxk[3] = {s_mx[0], s_mx[1], s_mx[2]};
    float sm[3] = {0.f, 0.f, 0.f};
    for (int e = tid; e < cnt; e += 256) {
#pragma unroll
        for (int k = 0; k < 3; k++) {
            float s = s_p[k][e];
            float p = (s != 0.f) ? __expf(s - mxk[k]) : 0.f;
            s_p[k][e] = p;
            sm[k] += p;
        }
    }
#pragma unroll
    for (int k = 0; k < 3; k++)
#pragma unroll
        for (int o = 16; o; o >>= 1)
            sm[k] += __shfl_xor_sync(0xffffffffu, sm[k], o);
    if (lane == 0) {
#pragma unroll
        for (int k = 0; k < 3; k++) s_red[k][wid] = sm[k];
    }
    __syncthreads();
    if (tid == 0) {
#pragma unroll
        for (int k = 0; k < 3; k++) {
            float t = 0.f;
#pragma unroll
            for (int w = 0; w < 8; w++) t += s_red[k][w];
            s_inv[k] = (t > 0.f) ? (1.0f / t) : 0.f;
        }
    }
    __syncthreads();

    // ---- gather: thread = output channel d
    float acc0 = 0.f, acc1 = 0.f, acc2 = 0.f;
    const float* wxd = g_wx + tid;
    for (int e = 0; e < cnt; e++) {
        unsigned v = s_list[e];
        int m = (int)(v >> 6);
        float p0 = s_p[0][e];
        float p1 = s_p[1][e];
        float p2 = s_p[2][e];
        const float* base = wxd + (size_t)m * DOUT;
        if (p0 != 0.f) acc0 += p0 * base[0];
        if (p1 != 0.f) acc1 += p1 * base[(size_t)NN * DOUT];
        if (p2 != 0.f) acc2 += p2 * base[2 * (size_t)NN * DOUT];
    }

    float t = acc0 * s_inv[0] + acc1 * s_inv[1] + acc2 * s_inv[2];
    out[(size_t)n * DOUT + tid] = (t > 0.f) ? t : expm1f(t);
}

// ---------------------------------------------------------------------------
extern "C" void kernel_launch(void* const* d_in, const int* in_sizes, int n_in,
                              void* d_out, int out_size) {
    const float* x        = (const float*)d_in[0];
    const int*   supports = (const int*)d_in[1];
    const int*   atten    = (const int*)d_in[2];
    const float* Wt       = (const float*)d_in[3];
    const float* Wl       = (const float*)d_in[4];
    const float* Wr       = (const float*)d_in[5];
    float* out = (float*)d_out;

    dim3 g1(DOUT / 64, NN / 64, KH);
    gemm_wx_kernel<<<g1, 256>>>(x, Wt);

    dim3 g2(NN / 32, KH);
    alar_kernel<<<g2, 256>>>(Wl, Wr);

    attn_kernel<<<NN, 256>>>(supports, atten, out);
}